// round 8
// baseline (speedup 1.0000x reference)
#include <cuda_runtime.h>
#include <cuda_fp16.h>
#include <cstdint>
#include <math.h>

// Problem constants
#define NRAYS   8192
#define TSAMP   128
#define HID     128
#define SHDIM   16
#define RAYEXT  10.0f
#define NTHREADS 512

// ---------------- warp-level tensor-core helpers ----------------
__device__ __forceinline__ void ldsm_x4(uint32_t* r, uint32_t addr) {
    asm volatile("ldmatrix.sync.aligned.m8n8.x4.shared.b16 {%0,%1,%2,%3}, [%4];"
        : "=r"(r[0]), "=r"(r[1]), "=r"(r[2]), "=r"(r[3]) : "r"(addr));
}
__device__ __forceinline__ void ldsm_x4_t(uint32_t* r, uint32_t addr) {
    asm volatile("ldmatrix.sync.aligned.m8n8.x4.trans.shared.b16 {%0,%1,%2,%3}, [%4];"
        : "=r"(r[0]), "=r"(r[1]), "=r"(r[2]), "=r"(r[3]) : "r"(addr));
}
__device__ __forceinline__ void mma_f16(float* d, const uint32_t* a,
                                        uint32_t b0, uint32_t b1) {
    asm volatile("mma.sync.aligned.m16n8k16.row.col.f32.f16.f16.f32 "
        "{%0,%1,%2,%3}, {%4,%5,%6,%7}, {%8,%9}, {%0,%1,%2,%3};"
        : "+f"(d[0]), "+f"(d[1]), "+f"(d[2]), "+f"(d[3])
        : "r"(a[0]), "r"(a[1]), "r"(a[2]), "r"(a[3]), "r"(b0), "r"(b1));
}
__device__ __forceinline__ uint32_t smem_u32(const void* p) {
    uint32_t a;
    asm("{ .reg .u64 t; cvta.to.shared.u64 t, %1; cvt.u32.u64 %0, t; }"
        : "=r"(a) : "l"(p));
    return a;
}
__device__ __forceinline__ uint32_t pack_h2(__half a, __half b) {
    __half2 t = __halves2half2(a, b);
    return *reinterpret_cast<uint32_t*>(&t);
}

// ---------------- SMEM layout ----------------
#define TSTRIDE  272
#define OFF_A    0              // fp16 A tile, 256 * 272 = 69632
#define OFF_B    69632          // fp16 B tile, 128 * 272 = 34816
#define OFF_F    104448
// float-region offsets (in floats)
#define F_W1   0       // 384
#define F_B1   384     // 128
#define F_B2   512     // 128
#define F_WD   640     // 128
#define F_WC   768     // 432
#define F_BC   1200    // 4 (bc0,bc1,bc2,bd)
#define F_TS   1216    // 256
#define F_MSK  1472    // 256
#define F_WS   1728    // 16
#define F_RED  1744    // 64
#define F_RAY  1808    // 16 (2 rays x 8: tfar_c,dnorm,active,dx,dy,dz)
#define F_HD   1824    // 256*4
#define F_TOTAL 2848
#define SMEM_BYTES (OFF_F + F_TOTAL * 4)

__device__ __forceinline__ void sh3(float x, float y, float z, float* Y) {
    float x2 = x*x, y2 = y*y, z2 = z*z;
    float xy = x*y, yz = y*z, xz = x*z;
    Y[0]  = 0.282094791773878f;
    Y[1]  = -0.48860251190292f * y;
    Y[2]  = 0.48860251190292f * z;
    Y[3]  = -0.48860251190292f * x;
    Y[4]  = 1.0925484305920792f * xy;
    Y[5]  = -1.0925484305920792f * yz;
    Y[6]  = 0.94617469575756f * z2 - 0.31539156525252f;
    Y[7]  = -1.0925484305920792f * xz;
    Y[8]  = 0.5462742152960396f * (x2 - y2);
    Y[9]  = 0.5900435899266435f * y * (-3.0f * x2 + y2);
    Y[10] = 2.8906114426405538f * xy * z;
    Y[11] = 0.4570457994644658f * y * (1.0f - 5.0f * z2);
    Y[12] = 0.3731763325901154f * z * (5.0f * z2 - 3.0f);
    Y[13] = 0.4570457994644658f * x * (1.0f - 5.0f * z2);
    Y[14] = 1.445305721320277f * z * (x2 - y2);
    Y[15] = 0.5900435899266435f * x * (-x2 + 3.0f * y2);
}

__global__ __launch_bounds__(NTHREADS, 1)
void radiance_kernel(const float* __restrict__ origins,
                     const float* __restrict__ dirs,
                     const float* __restrict__ u,
                     const float* __restrict__ W1,
                     const float* __restrict__ b1,
                     const float* __restrict__ W2,
                     const float* __restrict__ b2,
                     const float* __restrict__ Wd,
                     const float* __restrict__ bd,
                     const float* __restrict__ Wc,
                     const float* __restrict__ bc,
                     float* __restrict__ out)
{
    extern __shared__ char smc[];
    float* sf   = (float*)(smc + OFF_F);
    float* sW1  = sf + F_W1;
    float* sB1  = sf + F_B1;
    float* sB2  = sf + F_B2;
    float* sWD  = sf + F_WD;
    float* sWC  = sf + F_WC;
    float* sBC  = sf + F_BC;
    float* sTS  = sf + F_TS;
    float* sMSK = sf + F_MSK;
    float* sWS  = sf + F_WS;
    float* sRED = sf + F_RED;
    float* sRAY = sf + F_RAY;
    float* sHD  = sf + F_HD;

    const uint32_t sbase = smem_u32(smc);
    const int tid  = threadIdx.x;
    const int wid  = tid >> 5;
    const int lane = tid & 31;

    // ================= one-time staging (persistent CTA) =================
    for (int i = tid; i < 384; i += NTHREADS) sW1[i] = W1[i];
    if (tid < 128) {
        sB1[tid] = b1[tid];
        sB2[tid] = b2[tid];
        sWD[tid] = Wd[tid];
    }
    for (int i = tid; i < 432; i += NTHREADS) sWC[i] = Wc[i];
    if (tid < 3) sBC[tid] = bc[tid];
    if (tid == 3) sBC[3] = bd[0];

    // W2 -> B fp16 [k][n] (native layout, coalesced; one static rounding)
    {
        #pragma unroll
        for (int g = 0; g < 8; g++) {
            int idx4 = g * NTHREADS + tid;     // 0..4095 (float4 index)
            int k    = idx4 >> 5;              // 0..127
            int n4   = (idx4 & 31) << 2;       // 0..124
            float4 v = __ldg((const float4*)W2 + idx4);
            uint32_t p0 = pack_h2(__float2half(v.x), __float2half(v.y));
            uint32_t p1 = pack_h2(__float2half(v.z), __float2half(v.w));
            uint32_t off = (uint32_t)(k * TSTRIDE + n4 * 2);
            *(uint2*)(smc + OFF_B + off) = make_uint2(p0, p1);
        }
    }
    __syncthreads();

    // GEMM addressing (fixed per thread):
    // Warp w owns A rows [16w, 16w+16) exclusively.
    const uint32_t aBase = sbase + OFF_A
        + (uint32_t)((wid*16 + (lane & 15)) * TSTRIDE + (lane >> 4) * 16);
    const int gg = lane >> 3, ii = lane & 7;
    const uint32_t bRow = (uint32_t)(((gg & 1)*8 + ii) * TSTRIDE + (gg >> 1) * 16);
    const uint32_t bBase = sbase + OFF_B + bRow;

    // Per-warp constants for the barrier-free front-end
    const int wridx = wid >> 3;                       // warp's ray (0/1)
    const int rloc  = (wid & 7) * 16 + (lane & 15);   // sample idx 0..127
    const int arow  = wid * 16 + (lane & 15);         // A-tile row 0..255

    // ================= persistent loop: 2 rays per iteration =================
    for (int r0 = blockIdx.x * 2; r0 < NRAYS; r0 += gridDim.x * 2) {

        // ======== BARRIER-FREE PER-WARP FRONT-END ========
        const int wr = r0 + wridx;
        const float ox = __ldg(origins + 3*wr + 0);
        const float oy = __ldg(origins + 3*wr + 1);
        const float oz = __ldg(origins + 3*wr + 2);
        const float dx = __ldg(dirs + 3*wr + 0);
        const float dy = __ldg(dirs + 3*wr + 1);
        const float dz = __ldg(dirs + 3*wr + 2);

        float i0 = 1.0f/dx, i1 = 1.0f/dy, i2 = 1.0f/dz;
        float a0 = (-1.0f - ox)*i0, b0 = (1.0f - ox)*i0;
        float a1 = (-1.0f - oy)*i1, b1_ = (1.0f - oy)*i1;
        float a2 = (-1.0f - oz)*i2, b2_ = (1.0f - oz)*i2;
        float mn0 = fminf(a0,b0), mx0 = fmaxf(a0,b0);
        float mn1 = fminf(a1,b1_), mx1 = fmaxf(a1,b1_);
        float mn2 = fminf(a2,b2_), mx2 = fmaxf(a2,b2_);
        float tnear = fmaxf(fmaxf(fmaxf(mn0, mn1), mn2), 0.0f);
        float tfar  = fminf(fminf(mx0, mx1), mx2);
        float activef = (tfar > tnear) ? 1.0f : 0.0f;
        float tfar_c = fmaxf(tfar, tnear + 1e-3f);
        float dnorm = sqrtf(dx*dx + dy*dy + dz*dz);

        if ((wid & 7) == 0 && lane == 0) {
            float* rs = sRAY + wridx*8;
            rs[0] = tfar_c; rs[1] = dnorm; rs[2] = activef;
            rs[3] = dx; rs[4] = dy; rs[5] = dz;
        }

        // sample position for this lane's row (lanes 16-31 duplicate 0-15; benign)
        float uu = __ldg(u + wr*TSAMP + rloc);
        float frac = ((float)rloc + uu) * (1.0f/(float)TSAMP);
        float ts = tnear + (tfar_c - tnear) * frac;
        float px = ox + dx*ts, py = oy + dy*ts, pz = oz + dz*ts;
        bool inb = (fabsf(px) <= 1.0f) && (fabsf(py) <= 1.0f) && (fabsf(pz) <= 1.0f);
        sTS[wridx*TSAMP + rloc] = ts;
        sMSK[wridx*TSAMP + rloc] = (inb && activef != 0.0f) ? 1.0f : 0.0f;

        // layer1 for own row, own k-half: A = relu(X@W1+b1) as fp16
        {
            const int j0 = (lane >> 4) * 64;
            #pragma unroll
            for (int g = 0; g < 8; g++) {
                uint32_t hp[4];
                #pragma unroll
                for (int i = 0; i < 8; i += 2) {
                    int j = j0 + g*8 + i;
                    float v0 = fmaf(px, sW1[j],
                               fmaf(py, sW1[128 + j],
                               fmaf(pz, sW1[256 + j], sB1[j])));
                    float v1 = fmaf(px, sW1[j + 1],
                               fmaf(py, sW1[128 + j + 1],
                               fmaf(pz, sW1[256 + j + 1], sB1[j + 1])));
                    v0 = fmaxf(v0, 0.0f);
                    v1 = fmaxf(v1, 0.0f);
                    hp[i >> 1] = pack_h2(__float2half(v0), __float2half(v1));
                }
                uint32_t off = (uint32_t)(arow * TSTRIDE + (j0 + g*8) * 2);
                *(uint4*)(smc + OFF_A + off) = make_uint4(hp[0], hp[1], hp[2], hp[3]);
            }
        }
        __syncwarp();   // own rows written by own warp only

        // ---------- GEMM + fused heads: two 64-col passes ----------
        float hd0 = 0.0f, hd1 = 0.0f;
        float c00 = 0.0f, c01 = 0.0f, c02 = 0.0f;
        float c10 = 0.0f, c11 = 0.0f, c12 = 0.0f;

        #pragma unroll
        for (int pass = 0; pass < 2; pass++) {
            float acc[8][4];
            #pragma unroll
            for (int j = 0; j < 8; j++)
                #pragma unroll
                for (int p = 0; p < 4; p++) acc[j][p] = 0.0f;

            const uint32_t bH = bBase + (uint32_t)(pass * 128);

            #pragma unroll
            for (int s = 0; s < 8; s++) {
                uint32_t ah[4];
                ldsm_x4(ah, aBase + s*32);
                #pragma unroll
                for (int jp = 0; jp < 4; jp++) {
                    uint32_t bh[4];
                    ldsm_x4_t(bh, bH + s*(16*TSTRIDE) + jp*32);
                    mma_f16(acc[2*jp],     ah, bh[0], bh[1]);
                    mma_f16(acc[2*jp + 1], ah, bh[2], bh[3]);
                }
            }

            // fold this pass's 64 cols into head partials
            const int cbase = pass * 64 + (lane & 3) * 2;
            #pragma unroll
            for (int j = 0; j < 8; j++) {
                int c = cbase + j*8;
                float2 b2v = *(const float2*)(sB2 + c);
                float2 wdv = *(const float2*)(sWD + c);
                float h00 = fmaxf(acc[j][0] + b2v.x, 0.0f);
                float h01 = fmaxf(acc[j][1] + b2v.y, 0.0f);
                float h80 = fmaxf(acc[j][2] + b2v.x, 0.0f);
                float h81 = fmaxf(acc[j][3] + b2v.y, 0.0f);
                hd0 = fmaf(h00, wdv.x, fmaf(h01, wdv.y, hd0));
                hd1 = fmaf(h80, wdv.x, fmaf(h81, wdv.y, hd1));
                float w0x = sWC[3*c+0], w0y = sWC[3*c+1], w0z = sWC[3*c+2];
                float w1x = sWC[3*c+3], w1y = sWC[3*c+4], w1z = sWC[3*c+5];
                c00 = fmaf(h00, w0x, fmaf(h01, w1x, c00));
                c01 = fmaf(h00, w0y, fmaf(h01, w1y, c01));
                c02 = fmaf(h00, w0z, fmaf(h01, w1z, c02));
                c10 = fmaf(h80, w0x, fmaf(h81, w1x, c10));
                c11 = fmaf(h80, w0y, fmaf(h81, w1y, c11));
                c12 = fmaf(h80, w0z, fmaf(h81, w1z, c12));
            }
        }

        // quad reduce over (lane&3), store per-row head vector
        #pragma unroll
        for (int o = 1; o <= 2; o <<= 1) {
            hd0 += __shfl_xor_sync(0xffffffffu, hd0, o);
            hd1 += __shfl_xor_sync(0xffffffffu, hd1, o);
            c00 += __shfl_xor_sync(0xffffffffu, c00, o);
            c01 += __shfl_xor_sync(0xffffffffu, c01, o);
            c02 += __shfl_xor_sync(0xffffffffu, c02, o);
            c10 += __shfl_xor_sync(0xffffffffu, c10, o);
            c11 += __shfl_xor_sync(0xffffffffu, c11, o);
            c12 += __shfl_xor_sync(0xffffffffu, c12, o);
        }
        if ((lane & 3) == 0) {
            int row = wid*16 + (lane >> 2);
            sHD[row*4 + 0] = hd0;
            sHD[row*4 + 1] = c00;
            sHD[row*4 + 2] = c01;
            sHD[row*4 + 3] = c02;
            sHD[(row+8)*4 + 0] = hd1;
            sHD[(row+8)*4 + 1] = c10;
            sHD[(row+8)*4 + 2] = c11;
            sHD[(row+8)*4 + 3] = c12;
        }
        __syncthreads();   // barrier 1: sHD/sTS/sMSK/sRAY ready block-wide

        // ======== EPILOGUE (threads < 256; tid = global sample row) ========
        float my_sd = 0.0f, mc0 = 0.0f, mc1 = 0.0f, mc2 = 0.0f;
        if (tid < 2*TSAMP) {
            const float* rs = sRAY + ((tid >> 7) & 1) * 8;
            float e_tfar_c = rs[0];
            float e_dnorm = rs[1];
            float edx = rs[3], edy = rs[4], edz = rs[5];

            float accd = sHD[tid*4 + 0];
            float ac0  = sHD[tid*4 + 1];
            float ac1  = sHD[tid*4 + 2];
            float ac2  = sHD[tid*4 + 3];
            float inv_n = 1.0f / e_dnorm;
            float Ysh[16];
            sh3(edx*inv_n, edy*inv_n, edz*inv_n, Ysh);
            #pragma unroll
            for (int q = 0; q < SHDIM; q++) {
                float wq = Ysh[q];
                ac0 = fmaf(wq, sWC[(HID + q)*3 + 0], ac0);
                ac1 = fmaf(wq, sWC[(HID + q)*3 + 1], ac1);
                ac2 = fmaf(wq, sWC[(HID + q)*3 + 2], ac2);
            }
            float zz = accd + sBC[3];
            float sig = fmaxf(zz, 0.0f) + log1pf(expf(-fabsf(zz)));
            float m = sMSK[tid];
            sig *= m;
            mc0 = m / (1.0f + expf(-(ac0 + sBC[0])));
            mc1 = m / (1.0f + expf(-(ac1 + sBC[1])));
            mc2 = m / (1.0f + expf(-(ac2 + sBC[2])));
            float tsv  = sTS[tid];
            float tnxt = ((tid & 127) < TSAMP - 1) ? sTS[tid + 1] : (e_tfar_c * RAYEXT);
            my_sd = sig * (tnxt - tsv) * e_dnorm;
        }

        // two independent inclusive scans (warps 0-3 ray0, 4-7 ray1)
        float v = my_sd;
        #pragma unroll
        for (int o = 1; o < 32; o <<= 1) {
            float n = __shfl_up_sync(0xffffffffu, v, o);
            if (lane >= o) v += n;
        }
        if (wid < 8 && lane == 31) sWS[wid] = v;
        __syncthreads();
        float woff = 0.0f;
        if (wid < 8) {
            int qb = wid & ~3;
            #pragma unroll
            for (int d = 0; d < 4; d++) {
                int q = qb + d;
                woff += (q < wid) ? sWS[q] : 0.0f;
            }
        }
        float csum = v + woff;

        float wgt = 0.0f;
        if (tid < 2*TSAMP) wgt = expf(my_sd - csum) - expf(-csum);
        float rc0 = wgt * mc0, rc1 = wgt * mc1, rc2 = wgt * mc2;

        #pragma unroll
        for (int o = 16; o; o >>= 1) {
            rc0 += __shfl_xor_sync(0xffffffffu, rc0, o);
            rc1 += __shfl_xor_sync(0xffffffffu, rc1, o);
            rc2 += __shfl_xor_sync(0xffffffffu, rc2, o);
            wgt += __shfl_xor_sync(0xffffffffu, wgt, o);
        }
        if (wid < 8 && lane == 0) {
            sRED[wid*4 + 0] = rc0;
            sRED[wid*4 + 1] = rc1;
            sRED[wid*4 + 2] = rc2;
            sRED[wid*4 + 3] = wgt;
        }
        __syncthreads();
        if (tid == 0 || tid == 128) {
            int er = (tid >> 7) & 1;
            int qb = er * 4;
            float o0 = 0.0f, o1 = 0.0f, o2 = 0.0f, o3 = 0.0f;
            #pragma unroll
            for (int d = 0; d < 4; d++) {
                o0 += sRED[(qb+d)*4 + 0];
                o1 += sRED[(qb+d)*4 + 1];
                o2 += sRED[(qb+d)*4 + 2];
                o3 += sRED[(qb+d)*4 + 3];
            }
            bool act = (sRAY[er*8 + 2] != 0.0f);
            float4 res;
            res.x = act ? o0 : 0.0f;
            res.y = act ? o1 : 0.0f;
            res.z = act ? o2 : 0.0f;
            res.w = act ? o3 : 0.0f;
            *(float4*)(out + (size_t)(r0 + er)*4) = res;
        }
        __syncthreads();   // protect shared scratch before next iteration
    }
}

extern "C" void kernel_launch(void* const* d_in, const int* in_sizes, int n_in,
                              void* d_out, int out_size) {
    const float* origins = (const float*)d_in[0];
    const float* dirs    = (const float*)d_in[1];
    const float* u       = (const float*)d_in[2];
    const float* W1      = (const float*)d_in[3];
    const float* b1      = (const float*)d_in[4];
    const float* W2      = (const float*)d_in[5];
    const float* b2      = (const float*)d_in[6];
    const float* Wd      = (const float*)d_in[7];
    const float* bd      = (const float*)d_in[8];
    const float* Wc      = (const float*)d_in[9];
    const float* bc      = (const float*)d_in[10];
    float* out = (float*)d_out;

    int dev = 0, nsm = 148;
    cudaGetDevice(&dev);
    cudaDeviceGetAttribute(&nsm, cudaDevAttrMultiProcessorCount, dev);

    cudaFuncSetAttribute(radiance_kernel,
                         cudaFuncAttributeMaxDynamicSharedMemorySize, SMEM_BYTES);
    radiance_kernel<<<nsm, NTHREADS, SMEM_BYTES>>>(
        origins, dirs, u, W1, b1, W2, b2, Wd, bd, Wc, bc, out);
}

// round 9
// speedup vs baseline: 1.4492x; 1.4492x over previous
#include <cuda_runtime.h>
#include <cuda_fp16.h>
#include <cstdint>
#include <math.h>

// Problem constants
#define NRAYS   8192
#define TSAMP   128
#define HID     128
#define SHDIM   16
#define RAYEXT  10.0f
#define NTHREADS 512

// ---------------- warp-level tensor-core helpers ----------------
__device__ __forceinline__ void ldsm_x4(uint32_t* r, uint32_t addr) {
    asm volatile("ldmatrix.sync.aligned.m8n8.x4.shared.b16 {%0,%1,%2,%3}, [%4];"
        : "=r"(r[0]), "=r"(r[1]), "=r"(r[2]), "=r"(r[3]) : "r"(addr));
}
__device__ __forceinline__ void ldsm_x4_t(uint32_t* r, uint32_t addr) {
    asm volatile("ldmatrix.sync.aligned.m8n8.x4.trans.shared.b16 {%0,%1,%2,%3}, [%4];"
        : "=r"(r[0]), "=r"(r[1]), "=r"(r[2]), "=r"(r[3]) : "r"(addr));
}
__device__ __forceinline__ void mma_f16(float* d, const uint32_t* a,
                                        uint32_t b0, uint32_t b1) {
    asm volatile("mma.sync.aligned.m16n8k16.row.col.f32.f16.f16.f32 "
        "{%0,%1,%2,%3}, {%4,%5,%6,%7}, {%8,%9}, {%0,%1,%2,%3};"
        : "+f"(d[0]), "+f"(d[1]), "+f"(d[2]), "+f"(d[3])
        : "r"(a[0]), "r"(a[1]), "r"(a[2]), "r"(a[3]), "r"(b0), "r"(b1));
}
__device__ __forceinline__ uint32_t smem_u32(const void* p) {
    uint32_t a;
    asm("{ .reg .u64 t; cvta.to.shared.u64 t, %1; cvt.u32.u64 %0, t; }"
        : "=r"(a) : "l"(p));
    return a;
}
__device__ __forceinline__ uint32_t pack_h2(__half a, __half b) {
    __half2 t = __halves2half2(a, b);
    return *reinterpret_cast<uint32_t*>(&t);
}

// ---------------- SMEM layout ----------------
#define TSTRIDE  272
#define OFF_A    0              // fp16 A tile, 256 * 272 = 69632
#define OFF_B    69632          // fp16 B tile, 128 * 272 = 34816
#define OFF_F    104448
// float-region offsets (in floats)
#define F_W1   0       // 384
#define F_B1   384     // 128
#define F_B2   512     // 128
#define F_WD   640     // 128
#define F_WC   768     // 432
#define F_BC   1200    // 4 (bc0,bc1,bc2,bd)
#define F_TS   1216    // 256
#define F_MSK  1472    // 256
#define F_WS   1728    // 16
#define F_RED  1744    // 64
#define F_RAY  1808    // 16
#define F_HA   1824    // 256*4 (heads, col-half 0)
#define F_HB   2848    // 256*4 (heads, col-half 1)
#define F_TOTAL 3872
#define SMEM_BYTES (OFF_F + F_TOTAL * 4)

__device__ __forceinline__ void sh3(float x, float y, float z, float* Y) {
    float x2 = x*x, y2 = y*y, z2 = z*z;
    float xy = x*y, yz = y*z, xz = x*z;
    Y[0]  = 0.282094791773878f;
    Y[1]  = -0.48860251190292f * y;
    Y[2]  = 0.48860251190292f * z;
    Y[3]  = -0.48860251190292f * x;
    Y[4]  = 1.0925484305920792f * xy;
    Y[5]  = -1.0925484305920792f * yz;
    Y[6]  = 0.94617469575756f * z2 - 0.31539156525252f;
    Y[7]  = -1.0925484305920792f * xz;
    Y[8]  = 0.5462742152960396f * (x2 - y2);
    Y[9]  = 0.5900435899266435f * y * (-3.0f * x2 + y2);
    Y[10] = 2.8906114426405538f * xy * z;
    Y[11] = 0.4570457994644658f * y * (1.0f - 5.0f * z2);
    Y[12] = 0.3731763325901154f * z * (5.0f * z2 - 3.0f);
    Y[13] = 0.4570457994644658f * x * (1.0f - 5.0f * z2);
    Y[14] = 1.445305721320277f * z * (x2 - y2);
    Y[15] = 0.5900435899266435f * x * (-x2 + 3.0f * y2);
}

__global__ __launch_bounds__(NTHREADS, 1)
void radiance_kernel(const float* __restrict__ origins,
                     const float* __restrict__ dirs,
                     const float* __restrict__ u,
                     const float* __restrict__ W1,
                     const float* __restrict__ b1,
                     const float* __restrict__ W2,
                     const float* __restrict__ b2,
                     const float* __restrict__ Wd,
                     const float* __restrict__ bd,
                     const float* __restrict__ Wc,
                     const float* __restrict__ bc,
                     float* __restrict__ out)
{
    extern __shared__ char smc[];
    float* sf   = (float*)(smc + OFF_F);
    float* sW1  = sf + F_W1;
    float* sB1  = sf + F_B1;
    float* sB2  = sf + F_B2;
    float* sWD  = sf + F_WD;
    float* sWC  = sf + F_WC;
    float* sBC  = sf + F_BC;
    float* sTS  = sf + F_TS;
    float* sMSK = sf + F_MSK;
    float* sWS  = sf + F_WS;
    float* sRED = sf + F_RED;
    float* sRAY = sf + F_RAY;
    float* sHA  = sf + F_HA;
    float* sHB  = sf + F_HB;

    const uint32_t sbase = smem_u32(smc);
    const int tid  = threadIdx.x;
    const int wid  = tid >> 5;
    const int lane = tid & 31;

    // ================= one-time staging (persistent CTA) =================
    for (int i = tid; i < 384; i += NTHREADS) sW1[i] = W1[i];
    if (tid < 128) {
        sB1[tid] = b1[tid];
        sB2[tid] = b2[tid];
        sWD[tid] = Wd[tid];
    }
    for (int i = tid; i < 432; i += NTHREADS) sWC[i] = Wc[i];
    if (tid < 3) sBC[tid] = bc[tid];
    if (tid == 3) sBC[3] = bd[0];

    // W2 -> B fp16 [k][n] (native layout, coalesced; one static rounding)
    {
        #pragma unroll
        for (int g = 0; g < 8; g++) {
            int idx4 = g * NTHREADS + tid;     // 0..4095 (float4 index)
            int k    = idx4 >> 5;              // 0..127
            int n4   = (idx4 & 31) << 2;       // 0..124
            float4 v = __ldg((const float4*)W2 + idx4);
            uint32_t p0 = pack_h2(__float2half(v.x), __float2half(v.y));
            uint32_t p1 = pack_h2(__float2half(v.z), __float2half(v.w));
            uint32_t off = (uint32_t)(k * TSTRIDE + n4 * 2);
            *(uint2*)(smc + OFF_B + off) = make_uint2(p0, p1);
        }
    }
    __syncthreads();

    // GEMM addressing: warp w owns rows [32*(w>>1), +32) (two 16-row slabs)
    // and col half 64*(w&1).
    const int qw = wid >> 1;           // row block 0..7
    const int ch = wid & 1;            // col half 0/1
    const uint32_t aBase0 = sbase + OFF_A
        + (uint32_t)((qw*32 + (lane & 15)) * TSTRIDE + (lane >> 4) * 16);
    const uint32_t aBase1 = aBase0 + (uint32_t)(16 * TSTRIDE);
    const int gg = lane >> 3, ii = lane & 7;
    const uint32_t bRow = (uint32_t)(((gg & 1)*8 + ii) * TSTRIDE + (gg >> 1) * 16);
    const uint32_t bBase = sbase + OFF_B + bRow + (uint32_t)(ch * 128);

    // Per-warp constants for the front-end
    const int wridx = wid >> 3;                       // warp's ray (0/1)
    const int rloc  = (wid & 7) * 16 + (lane & 15);   // sample idx 0..127
    const int arow  = wid * 16 + (lane & 15);         // A-tile row 0..255

    // ================= persistent loop: 2 rays per iteration =================
    for (int r0 = blockIdx.x * 2; r0 < NRAYS; r0 += gridDim.x * 2) {

        // ======== PER-WARP FRONT-END ========
        const int wr = r0 + wridx;
        const float ox = __ldg(origins + 3*wr + 0);
        const float oy = __ldg(origins + 3*wr + 1);
        const float oz = __ldg(origins + 3*wr + 2);
        const float dx = __ldg(dirs + 3*wr + 0);
        const float dy = __ldg(dirs + 3*wr + 1);
        const float dz = __ldg(dirs + 3*wr + 2);

        float i0 = 1.0f/dx, i1 = 1.0f/dy, i2 = 1.0f/dz;
        float a0 = (-1.0f - ox)*i0, b0 = (1.0f - ox)*i0;
        float a1 = (-1.0f - oy)*i1, b1_ = (1.0f - oy)*i1;
        float a2 = (-1.0f - oz)*i2, b2_ = (1.0f - oz)*i2;
        float mn0 = fminf(a0,b0), mx0 = fmaxf(a0,b0);
        float mn1 = fminf(a1,b1_), mx1 = fmaxf(a1,b1_);
        float mn2 = fminf(a2,b2_), mx2 = fmaxf(a2,b2_);
        float tnear = fmaxf(fmaxf(fmaxf(mn0, mn1), mn2), 0.0f);
        float tfar  = fminf(fminf(mx0, mx1), mx2);
        float activef = (tfar > tnear) ? 1.0f : 0.0f;
        float tfar_c = fmaxf(tfar, tnear + 1e-3f);
        float dnorm = sqrtf(dx*dx + dy*dy + dz*dz);

        if ((wid & 7) == 0 && lane == 0) {
            float* rs = sRAY + wridx*8;
            rs[0] = tfar_c; rs[1] = dnorm; rs[2] = activef;
            rs[3] = dx; rs[4] = dy; rs[5] = dz;
        }

        // sample position for this lane's row
        float uu = __ldg(u + wr*TSAMP + rloc);
        float frac = ((float)rloc + uu) * (1.0f/(float)TSAMP);
        float ts = tnear + (tfar_c - tnear) * frac;
        float px = ox + dx*ts, py = oy + dy*ts, pz = oz + dz*ts;
        bool inb = (fabsf(px) <= 1.0f) && (fabsf(py) <= 1.0f) && (fabsf(pz) <= 1.0f);
        sTS[wridx*TSAMP + rloc] = ts;
        sMSK[wridx*TSAMP + rloc] = (inb && activef != 0.0f) ? 1.0f : 0.0f;

        // layer1 for own row, own k-half: A = relu(X@W1+b1) as fp16
        {
            const int j0 = (lane >> 4) * 64;
            #pragma unroll
            for (int g = 0; g < 8; g++) {
                uint32_t hp[4];
                #pragma unroll
                for (int i = 0; i < 8; i += 2) {
                    int j = j0 + g*8 + i;
                    float v0 = fmaf(px, sW1[j],
                               fmaf(py, sW1[128 + j],
                               fmaf(pz, sW1[256 + j], sB1[j])));
                    float v1 = fmaf(px, sW1[j + 1],
                               fmaf(py, sW1[128 + j + 1],
                               fmaf(pz, sW1[256 + j + 1], sB1[j + 1])));
                    v0 = fmaxf(v0, 0.0f);
                    v1 = fmaxf(v1, 0.0f);
                    hp[i >> 1] = pack_h2(__float2half(v0), __float2half(v1));
                }
                uint32_t off = (uint32_t)(arow * TSTRIDE + (j0 + g*8) * 2);
                *(uint4*)(smc + OFF_A + off) = make_uint4(hp[0], hp[1], hp[2], hp[3]);
            }
        }
        __syncthreads();   // warp pairs read each other's A rows

        // ---------- GEMM: 32 rows x 64 cols per warp, B fragments reused x4 ----------
        float acc0[8][4], acc1[8][4];
        #pragma unroll
        for (int j = 0; j < 8; j++)
            #pragma unroll
            for (int p = 0; p < 4; p++) { acc0[j][p] = 0.0f; acc1[j][p] = 0.0f; }

        #pragma unroll
        for (int s = 0; s < 8; s++) {
            uint32_t ah0[4], ah1[4];
            ldsm_x4(ah0, aBase0 + s*32);
            ldsm_x4(ah1, aBase1 + s*32);
            #pragma unroll
            for (int jp = 0; jp < 4; jp++) {
                uint32_t bh[4];
                ldsm_x4_t(bh, bBase + s*(16*TSTRIDE) + jp*32);
                mma_f16(acc0[2*jp],     ah0, bh[0], bh[1]);
                mma_f16(acc0[2*jp + 1], ah0, bh[2], bh[3]);
                mma_f16(acc1[2*jp],     ah1, bh[0], bh[1]);
                mma_f16(acc1[2*jp + 1], ah1, bh[2], bh[3]);
            }
        }

        // ---------- fused heads per slab ----------
        float* dst = ch ? sHB : sHA;
        const int cbase = ch * 64 + (lane & 3) * 2;
        #pragma unroll
        for (int sl = 0; sl < 2; sl++) {
            float hd0 = 0.0f, hd1 = 0.0f;
            float c00 = 0.0f, c01 = 0.0f, c02 = 0.0f;
            float c10 = 0.0f, c11 = 0.0f, c12 = 0.0f;
            #pragma unroll
            for (int j = 0; j < 8; j++) {
                float* av = sl ? acc1[j] : acc0[j];
                int c = cbase + j*8;
                float2 b2v = *(const float2*)(sB2 + c);
                float2 wdv = *(const float2*)(sWD + c);
                float h00 = fmaxf(av[0] + b2v.x, 0.0f);
                float h01 = fmaxf(av[1] + b2v.y, 0.0f);
                float h80 = fmaxf(av[2] + b2v.x, 0.0f);
                float h81 = fmaxf(av[3] + b2v.y, 0.0f);
                hd0 = fmaf(h00, wdv.x, fmaf(h01, wdv.y, hd0));
                hd1 = fmaf(h80, wdv.x, fmaf(h81, wdv.y, hd1));
                float w0x = sWC[3*c+0], w0y = sWC[3*c+1], w0z = sWC[3*c+2];
                float w1x = sWC[3*c+3], w1y = sWC[3*c+4], w1z = sWC[3*c+5];
                c00 = fmaf(h00, w0x, fmaf(h01, w1x, c00));
                c01 = fmaf(h00, w0y, fmaf(h01, w1y, c01));
                c02 = fmaf(h00, w0z, fmaf(h01, w1z, c02));
                c10 = fmaf(h80, w0x, fmaf(h81, w1x, c10));
                c11 = fmaf(h80, w0y, fmaf(h81, w1y, c11));
                c12 = fmaf(h80, w0z, fmaf(h81, w1z, c12));
            }
            #pragma unroll
            for (int o = 1; o <= 2; o <<= 1) {
                hd0 += __shfl_xor_sync(0xffffffffu, hd0, o);
                hd1 += __shfl_xor_sync(0xffffffffu, hd1, o);
                c00 += __shfl_xor_sync(0xffffffffu, c00, o);
                c01 += __shfl_xor_sync(0xffffffffu, c01, o);
                c02 += __shfl_xor_sync(0xffffffffu, c02, o);
                c10 += __shfl_xor_sync(0xffffffffu, c10, o);
                c11 += __shfl_xor_sync(0xffffffffu, c11, o);
                c12 += __shfl_xor_sync(0xffffffffu, c12, o);
            }
            if ((lane & 3) == 0) {
                int row = qw*32 + sl*16 + (lane >> 2);
                dst[row*4 + 0] = hd0;
                dst[row*4 + 1] = c00;
                dst[row*4 + 2] = c01;
                dst[row*4 + 3] = c02;
                dst[(row+8)*4 + 0] = hd1;
                dst[(row+8)*4 + 1] = c10;
                dst[(row+8)*4 + 2] = c11;
                dst[(row+8)*4 + 3] = c12;
            }
        }
        __syncthreads();   // sHA/sHB/sTS/sMSK/sRAY ready block-wide

        // ======== EPILOGUE (threads < 256; tid = global sample row) ========
        float my_sd = 0.0f, mc0 = 0.0f, mc1 = 0.0f, mc2 = 0.0f;
        if (tid < 2*TSAMP) {
            const float* rs = sRAY + ((tid >> 7) & 1) * 8;
            float e_tfar_c = rs[0];
            float e_dnorm = rs[1];
            float edx = rs[3], edy = rs[4], edz = rs[5];

            float accd = sHA[tid*4 + 0] + sHB[tid*4 + 0];
            float ac0  = sHA[tid*4 + 1] + sHB[tid*4 + 1];
            float ac1  = sHA[tid*4 + 2] + sHB[tid*4 + 2];
            float ac2  = sHA[tid*4 + 3] + sHB[tid*4 + 3];
            float inv_n = 1.0f / e_dnorm;
            float Ysh[16];
            sh3(edx*inv_n, edy*inv_n, edz*inv_n, Ysh);
            #pragma unroll
            for (int q = 0; q < SHDIM; q++) {
                float wq = Ysh[q];
                ac0 = fmaf(wq, sWC[(HID + q)*3 + 0], ac0);
                ac1 = fmaf(wq, sWC[(HID + q)*3 + 1], ac1);
                ac2 = fmaf(wq, sWC[(HID + q)*3 + 2], ac2);
            }
            float zz = accd + sBC[3];
            float sig = fmaxf(zz, 0.0f) + log1pf(expf(-fabsf(zz)));
            float m = sMSK[tid];
            sig *= m;
            mc0 = m / (1.0f + expf(-(ac0 + sBC[0])));
            mc1 = m / (1.0f + expf(-(ac1 + sBC[1])));
            mc2 = m / (1.0f + expf(-(ac2 + sBC[2])));
            float tsv  = sTS[tid];
            float tnxt = ((tid & 127) < TSAMP - 1) ? sTS[tid + 1] : (e_tfar_c * RAYEXT);
            my_sd = sig * (tnxt - tsv) * e_dnorm;
        }

        // two independent inclusive scans (warps 0-3 ray0, 4-7 ray1)
        float v = my_sd;
        #pragma unroll
        for (int o = 1; o < 32; o <<= 1) {
            float n = __shfl_up_sync(0xffffffffu, v, o);
            if (lane >= o) v += n;
        }
        if (wid < 8 && lane == 31) sWS[wid] = v;
        __syncthreads();
        float woff = 0.0f;
        if (wid < 8) {
            int qb = wid & ~3;
            #pragma unroll
            for (int d = 0; d < 4; d++) {
                int q = qb + d;
                woff += (q < wid) ? sWS[q] : 0.0f;
            }
        }
        float csum = v + woff;

        float wgt = 0.0f;
        if (tid < 2*TSAMP) wgt = expf(my_sd - csum) - expf(-csum);
        float rc0 = wgt * mc0, rc1 = wgt * mc1, rc2 = wgt * mc2;

        #pragma unroll
        for (int o = 16; o; o >>= 1) {
            rc0 += __shfl_xor_sync(0xffffffffu, rc0, o);
            rc1 += __shfl_xor_sync(0xffffffffu, rc1, o);
            rc2 += __shfl_xor_sync(0xffffffffu, rc2, o);
            wgt += __shfl_xor_sync(0xffffffffu, wgt, o);
        }
        if (wid < 8 && lane == 0) {
            sRED[wid*4 + 0] = rc0;
            sRED[wid*4 + 1] = rc1;
            sRED[wid*4 + 2] = rc2;
            sRED[wid*4 + 3] = wgt;
        }
        __syncthreads();
        if (tid == 0 || tid == 128) {
            int er = (tid >> 7) & 1;
            int qb = er * 4;
            float o0 = 0.0f, o1 = 0.0f, o2 = 0.0f, o3 = 0.0f;
            #pragma unroll
            for (int d = 0; d < 4; d++) {
                o0 += sRED[(qb+d)*4 + 0];
                o1 += sRED[(qb+d)*4 + 1];
                o2 += sRED[(qb+d)*4 + 2];
                o3 += sRED[(qb+d)*4 + 3];
            }
            bool act = (sRAY[er*8 + 2] != 0.0f);
            float4 res;
            res.x = act ? o0 : 0.0f;
            res.y = act ? o1 : 0.0f;
            res.z = act ? o2 : 0.0f;
            res.w = act ? o3 : 0.0f;
            *(float4*)(out + (size_t)(r0 + er)*4) = res;
        }
        __syncthreads();   // protect shared scratch before next iteration
    }
}

extern "C" void kernel_launch(void* const* d_in, const int* in_sizes, int n_in,
                              void* d_out, int out_size) {
    const float* origins = (const float*)d_in[0];
    const float* dirs    = (const float*)d_in[1];
    const float* u       = (const float*)d_in[2];
    const float* W1      = (const float*)d_in[3];
    const float* b1      = (const float*)d_in[4];
    const float* W2      = (const float*)d_in[5];
    const float* b2      = (const float*)d_in[6];
    const float* Wd      = (const float*)d_in[7];
    const float* bd      = (const float*)d_in[8];
    const float* Wc      = (const float*)d_in[9];
    const float* bc      = (const float*)d_in[10];
    float* out = (float*)d_out;

    int dev = 0, nsm = 148;
    cudaGetDevice(&dev);
    cudaDeviceGetAttribute(&nsm, cudaDevAttrMultiProcessorCount, dev);

    cudaFuncSetAttribute(radiance_kernel,
                         cudaFuncAttributeMaxDynamicSharedMemorySize, SMEM_BYTES);
    radiance_kernel<<<nsm, NTHREADS, SMEM_BYTES>>>(
        origins, dirs, u, W1, b1, W2, b2, Wd, bd, Wc, bc, out);
}

// round 10
// speedup vs baseline: 1.7282x; 1.1925x over previous
#include <cuda_runtime.h>
#include <cuda_fp16.h>
#include <cstdint>
#include <math.h>

// Problem constants
#define NRAYS   8192
#define TSAMP   128
#define HID     128
#define SHDIM   16
#define RAYEXT  10.0f
#define NTHREADS 256

// ---------------- warp-level tensor-core helpers ----------------
__device__ __forceinline__ void ldsm_x4(uint32_t* r, uint32_t addr) {
    asm volatile("ldmatrix.sync.aligned.m8n8.x4.shared.b16 {%0,%1,%2,%3}, [%4];"
        : "=r"(r[0]), "=r"(r[1]), "=r"(r[2]), "=r"(r[3]) : "r"(addr));
}
__device__ __forceinline__ void ldsm_x4_t(uint32_t* r, uint32_t addr) {
    asm volatile("ldmatrix.sync.aligned.m8n8.x4.trans.shared.b16 {%0,%1,%2,%3}, [%4];"
        : "=r"(r[0]), "=r"(r[1]), "=r"(r[2]), "=r"(r[3]) : "r"(addr));
}
__device__ __forceinline__ void mma_f16(float* d, const uint32_t* a,
                                        uint32_t b0, uint32_t b1) {
    asm volatile("mma.sync.aligned.m16n8k16.row.col.f32.f16.f16.f32 "
        "{%0,%1,%2,%3}, {%4,%5,%6,%7}, {%8,%9}, {%0,%1,%2,%3};"
        : "+f"(d[0]), "+f"(d[1]), "+f"(d[2]), "+f"(d[3])
        : "r"(a[0]), "r"(a[1]), "r"(a[2]), "r"(a[3]), "r"(b0), "r"(b1));
}
__device__ __forceinline__ uint32_t smem_u32(const void* p) {
    uint32_t a;
    asm("{ .reg .u64 t; cvta.to.shared.u64 t, %1; cvt.u32.u64 %0, t; }"
        : "=r"(a) : "l"(p));
    return a;
}
__device__ __forceinline__ uint32_t pack_h2(__half a, __half b) {
    __half2 t = __halves2half2(a, b);
    return *reinterpret_cast<uint32_t*>(&t);
}

// ---------------- SMEM layout (per CTA) ----------------
#define TSTRIDE  272
#define OFF_A    0              // fp16 A tile, 128 * 272 = 34816
#define OFF_B    34816          // fp16 B tile, 128 * 272 = 34816
#define OFF_F    69632
// float-region offsets (in floats)
#define F_W1   0       // 384
#define F_B1   384     // 128
#define F_B2   512     // 128
#define F_WD   640     // 128
#define F_WC   768     // 432
#define F_BC   1200    // 4 (bc0,bc1,bc2,bd)
#define F_TS   1216    // 128
#define F_MSK  1344    // 128
#define F_WS   1472    // 8
#define F_RED  1480    // 16
#define F_RAY  1496    // 8
#define F_HA   1504    // 128*4 (heads, col-half 0)
#define F_HB   2016    // 128*4 (heads, col-half 1)
#define F_TOTAL 2528
#define SMEM_BYTES (OFF_F + F_TOTAL * 4)

__device__ __forceinline__ void sh3(float x, float y, float z, float* Y) {
    float x2 = x*x, y2 = y*y, z2 = z*z;
    float xy = x*y, yz = y*z, xz = x*z;
    Y[0]  = 0.282094791773878f;
    Y[1]  = -0.48860251190292f * y;
    Y[2]  = 0.48860251190292f * z;
    Y[3]  = -0.48860251190292f * x;
    Y[4]  = 1.0925484305920792f * xy;
    Y[5]  = -1.0925484305920792f * yz;
    Y[6]  = 0.94617469575756f * z2 - 0.31539156525252f;
    Y[7]  = -1.0925484305920792f * xz;
    Y[8]  = 0.5462742152960396f * (x2 - y2);
    Y[9]  = 0.5900435899266435f * y * (-3.0f * x2 + y2);
    Y[10] = 2.8906114426405538f * xy * z;
    Y[11] = 0.4570457994644658f * y * (1.0f - 5.0f * z2);
    Y[12] = 0.3731763325901154f * z * (5.0f * z2 - 3.0f);
    Y[13] = 0.4570457994644658f * x * (1.0f - 5.0f * z2);
    Y[14] = 1.445305721320277f * z * (x2 - y2);
    Y[15] = 0.5900435899266435f * x * (-x2 + 3.0f * y2);
}

__global__ __launch_bounds__(NTHREADS, 2)
void radiance_kernel(const float* __restrict__ origins,
                     const float* __restrict__ dirs,
                     const float* __restrict__ u,
                     const float* __restrict__ W1,
                     const float* __restrict__ b1,
                     const float* __restrict__ W2,
                     const float* __restrict__ b2,
                     const float* __restrict__ Wd,
                     const float* __restrict__ bd,
                     const float* __restrict__ Wc,
                     const float* __restrict__ bc,
                     float* __restrict__ out)
{
    extern __shared__ char smc[];
    float* sf   = (float*)(smc + OFF_F);
    float* sW1  = sf + F_W1;
    float* sB1  = sf + F_B1;
    float* sB2  = sf + F_B2;
    float* sWD  = sf + F_WD;
    float* sWC  = sf + F_WC;
    float* sBC  = sf + F_BC;
    float* sTS  = sf + F_TS;
    float* sMSK = sf + F_MSK;
    float* sWS  = sf + F_WS;
    float* sRED = sf + F_RED;
    float* sRAY = sf + F_RAY;
    float* sHA  = sf + F_HA;
    float* sHB  = sf + F_HB;

    const uint32_t sbase = smem_u32(smc);
    const int tid  = threadIdx.x;
    const int wid  = tid >> 5;
    const int lane = tid & 31;

    // ================= one-time staging (persistent CTA) =================
    for (int i = tid; i < 384; i += NTHREADS) sW1[i] = W1[i];
    if (tid < 128) {
        sB1[tid] = b1[tid];
        sB2[tid] = b2[tid];
        sWD[tid] = Wd[tid];
    }
    for (int i = tid; i < 432; i += NTHREADS) sWC[i] = Wc[i];
    if (tid < 3) sBC[tid] = bc[tid];
    if (tid == 3) sBC[3] = bd[0];

    // W2 -> B fp16 [k][n] (native layout, coalesced; one static rounding)
    {
        #pragma unroll
        for (int g = 0; g < 16; g++) {
            int idx4 = g * NTHREADS + tid;     // 0..4095 (float4 index)
            int k    = idx4 >> 5;              // 0..127
            int n4   = (idx4 & 31) << 2;       // 0..124
            float4 v = __ldg((const float4*)W2 + idx4);
            uint32_t p0 = pack_h2(__float2half(v.x), __float2half(v.y));
            uint32_t p1 = pack_h2(__float2half(v.z), __float2half(v.w));
            uint32_t off = (uint32_t)(k * TSTRIDE + n4 * 2);
            *(uint2*)(smc + OFF_B + off) = make_uint2(p0, p1);
        }
    }
    __syncthreads();

    // GEMM addressing: warp w owns rows [32*(w>>1), +32) (two 16-row slabs)
    // and col half 64*(w&1).
    const int qw = wid >> 1;           // row block 0..3
    const int ch = wid & 1;            // col half 0/1
    const uint32_t aBase0 = sbase + OFF_A
        + (uint32_t)((qw*32 + (lane & 15)) * TSTRIDE + (lane >> 4) * 16);
    const uint32_t aBase1 = aBase0 + (uint32_t)(16 * TSTRIDE);
    const int gg = lane >> 3, ii = lane & 7;
    const uint32_t bRow = (uint32_t)(((gg & 1)*8 + ii) * TSTRIDE + (gg >> 1) * 16);
    const uint32_t bBase = sbase + OFF_B + bRow + (uint32_t)(ch * 128);

    // Per-warp constants for the front-end
    const int rloc = wid * 16 + (lane & 15);   // sample idx 0..127
    const int arow = rloc;                     // A-tile row 0..127

    // ================= persistent loop: 1 ray per iteration, 2 CTAs/SM =========
    for (int r = blockIdx.x; r < NRAYS; r += gridDim.x) {

        // ======== PER-WARP FRONT-END ========
        const float ox = __ldg(origins + 3*r + 0);
        const float oy = __ldg(origins + 3*r + 1);
        const float oz = __ldg(origins + 3*r + 2);
        const float dx = __ldg(dirs + 3*r + 0);
        const float dy = __ldg(dirs + 3*r + 1);
        const float dz = __ldg(dirs + 3*r + 2);

        float i0 = 1.0f/dx, i1 = 1.0f/dy, i2 = 1.0f/dz;
        float a0 = (-1.0f - ox)*i0, b0 = (1.0f - ox)*i0;
        float a1 = (-1.0f - oy)*i1, b1_ = (1.0f - oy)*i1;
        float a2 = (-1.0f - oz)*i2, b2_ = (1.0f - oz)*i2;
        float mn0 = fminf(a0,b0), mx0 = fmaxf(a0,b0);
        float mn1 = fminf(a1,b1_), mx1 = fmaxf(a1,b1_);
        float mn2 = fminf(a2,b2_), mx2 = fmaxf(a2,b2_);
        float tnear = fmaxf(fmaxf(fmaxf(mn0, mn1), mn2), 0.0f);
        float tfar  = fminf(fminf(mx0, mx1), mx2);
        float activef = (tfar > tnear) ? 1.0f : 0.0f;
        float tfar_c = fmaxf(tfar, tnear + 1e-3f);
        float dnorm = sqrtf(dx*dx + dy*dy + dz*dz);

        if (tid == 0) {
            sRAY[0] = tfar_c; sRAY[1] = dnorm; sRAY[2] = activef;
            sRAY[3] = dx; sRAY[4] = dy; sRAY[5] = dz;
        }

        // sample position for this lane's row
        float uu = __ldg(u + r*TSAMP + rloc);
        float frac = ((float)rloc + uu) * (1.0f/(float)TSAMP);
        float ts = tnear + (tfar_c - tnear) * frac;
        float px = ox + dx*ts, py = oy + dy*ts, pz = oz + dz*ts;
        bool inb = (fabsf(px) <= 1.0f) && (fabsf(py) <= 1.0f) && (fabsf(pz) <= 1.0f);
        sTS[rloc] = ts;
        sMSK[rloc] = (inb && activef != 0.0f) ? 1.0f : 0.0f;

        // layer1 for own row, own k-half: A = relu(X@W1+b1) as fp16
        {
            const int j0 = (lane >> 4) * 64;
            #pragma unroll
            for (int g = 0; g < 8; g++) {
                uint32_t hp[4];
                #pragma unroll
                for (int i = 0; i < 8; i += 2) {
                    int j = j0 + g*8 + i;
                    float v0 = fmaf(px, sW1[j],
                               fmaf(py, sW1[128 + j],
                               fmaf(pz, sW1[256 + j], sB1[j])));
                    float v1 = fmaf(px, sW1[j + 1],
                               fmaf(py, sW1[128 + j + 1],
                               fmaf(pz, sW1[256 + j + 1], sB1[j + 1])));
                    v0 = fmaxf(v0, 0.0f);
                    v1 = fmaxf(v1, 0.0f);
                    hp[i >> 1] = pack_h2(__float2half(v0), __float2half(v1));
                }
                uint32_t off = (uint32_t)(arow * TSTRIDE + (j0 + g*8) * 2);
                *(uint4*)(smc + OFF_A + off) = make_uint4(hp[0], hp[1], hp[2], hp[3]);
            }
        }
        __syncthreads();   // warp pairs read each other's A rows

        // ---------- GEMM: 32 rows x 64 cols per warp, B fragments reused x4 ----------
        float acc0[8][4], acc1[8][4];
        #pragma unroll
        for (int j = 0; j < 8; j++)
            #pragma unroll
            for (int p = 0; p < 4; p++) { acc0[j][p] = 0.0f; acc1[j][p] = 0.0f; }

        #pragma unroll
        for (int s = 0; s < 8; s++) {
            uint32_t ah0[4], ah1[4];
            ldsm_x4(ah0, aBase0 + s*32);
            ldsm_x4(ah1, aBase1 + s*32);
            #pragma unroll
            for (int jp = 0; jp < 4; jp++) {
                uint32_t bh[4];
                ldsm_x4_t(bh, bBase + s*(16*TSTRIDE) + jp*32);
                mma_f16(acc0[2*jp],     ah0, bh[0], bh[1]);
                mma_f16(acc0[2*jp + 1], ah0, bh[2], bh[3]);
                mma_f16(acc1[2*jp],     ah1, bh[0], bh[1]);
                mma_f16(acc1[2*jp + 1], ah1, bh[2], bh[3]);
            }
        }

        // ---------- fused heads, both slabs in one pass (weights loaded once) ----
        float s0hd0 = 0.0f, s0hd1 = 0.0f, s0c00 = 0.0f, s0c01 = 0.0f, s0c02 = 0.0f;
        float s0c10 = 0.0f, s0c11 = 0.0f, s0c12 = 0.0f;
        float s1hd0 = 0.0f, s1hd1 = 0.0f, s1c00 = 0.0f, s1c01 = 0.0f, s1c02 = 0.0f;
        float s1c10 = 0.0f, s1c11 = 0.0f, s1c12 = 0.0f;
        const int cbase = ch * 64 + (lane & 3) * 2;
        #pragma unroll
        for (int j = 0; j < 8; j++) {
            int c = cbase + j*8;
            float2 b2v = *(const float2*)(sB2 + c);
            float2 wdv = *(const float2*)(sWD + c);
            float w0x = sWC[3*c+0], w0y = sWC[3*c+1], w0z = sWC[3*c+2];
            float w1x = sWC[3*c+3], w1y = sWC[3*c+4], w1z = sWC[3*c+5];

            float h00 = fmaxf(acc0[j][0] + b2v.x, 0.0f);
            float h01 = fmaxf(acc0[j][1] + b2v.y, 0.0f);
            float h80 = fmaxf(acc0[j][2] + b2v.x, 0.0f);
            float h81 = fmaxf(acc0[j][3] + b2v.y, 0.0f);
            s0hd0 = fmaf(h00, wdv.x, fmaf(h01, wdv.y, s0hd0));
            s0hd1 = fmaf(h80, wdv.x, fmaf(h81, wdv.y, s0hd1));
            s0c00 = fmaf(h00, w0x, fmaf(h01, w1x, s0c00));
            s0c01 = fmaf(h00, w0y, fmaf(h01, w1y, s0c01));
            s0c02 = fmaf(h00, w0z, fmaf(h01, w1z, s0c02));
            s0c10 = fmaf(h80, w0x, fmaf(h81, w1x, s0c10));
            s0c11 = fmaf(h80, w0y, fmaf(h81, w1y, s0c11));
            s0c12 = fmaf(h80, w0z, fmaf(h81, w1z, s0c12));

            float g00 = fmaxf(acc1[j][0] + b2v.x, 0.0f);
            float g01 = fmaxf(acc1[j][1] + b2v.y, 0.0f);
            float g80 = fmaxf(acc1[j][2] + b2v.x, 0.0f);
            float g81 = fmaxf(acc1[j][3] + b2v.y, 0.0f);
            s1hd0 = fmaf(g00, wdv.x, fmaf(g01, wdv.y, s1hd0));
            s1hd1 = fmaf(g80, wdv.x, fmaf(g81, wdv.y, s1hd1));
            s1c00 = fmaf(g00, w0x, fmaf(g01, w1x, s1c00));
            s1c01 = fmaf(g00, w0y, fmaf(g01, w1y, s1c01));
            s1c02 = fmaf(g00, w0z, fmaf(g01, w1z, s1c02));
            s1c10 = fmaf(g80, w0x, fmaf(g81, w1x, s1c10));
            s1c11 = fmaf(g80, w0y, fmaf(g81, w1y, s1c11));
            s1c12 = fmaf(g80, w0z, fmaf(g81, w1z, s1c12));
        }

        // quad reduce over (lane&3), store per-row head vectors
        #pragma unroll
        for (int o = 1; o <= 2; o <<= 1) {
            s0hd0 += __shfl_xor_sync(0xffffffffu, s0hd0, o);
            s0hd1 += __shfl_xor_sync(0xffffffffu, s0hd1, o);
            s0c00 += __shfl_xor_sync(0xffffffffu, s0c00, o);
            s0c01 += __shfl_xor_sync(0xffffffffu, s0c01, o);
            s0c02 += __shfl_xor_sync(0xffffffffu, s0c02, o);
            s0c10 += __shfl_xor_sync(0xffffffffu, s0c10, o);
            s0c11 += __shfl_xor_sync(0xffffffffu, s0c11, o);
            s0c12 += __shfl_xor_sync(0xffffffffu, s0c12, o);
            s1hd0 += __shfl_xor_sync(0xffffffffu, s1hd0, o);
            s1hd1 += __shfl_xor_sync(0xffffffffu, s1hd1, o);
            s1c00 += __shfl_xor_sync(0xffffffffu, s1c00, o);
            s1c01 += __shfl_xor_sync(0xffffffffu, s1c01, o);
            s1c02 += __shfl_xor_sync(0xffffffffu, s1c02, o);
            s1c10 += __shfl_xor_sync(0xffffffffu, s1c10, o);
            s1c11 += __shfl_xor_sync(0xffffffffu, s1c11, o);
            s1c12 += __shfl_xor_sync(0xffffffffu, s1c12, o);
        }
        if ((lane & 3) == 0) {
            float* dst = ch ? sHB : sHA;
            int row = qw*32 + (lane >> 2);
            dst[row*4 + 0] = s0hd0;
            dst[row*4 + 1] = s0c00;
            dst[row*4 + 2] = s0c01;
            dst[row*4 + 3] = s0c02;
            dst[(row+8)*4 + 0] = s0hd1;
            dst[(row+8)*4 + 1] = s0c10;
            dst[(row+8)*4 + 2] = s0c11;
            dst[(row+8)*4 + 3] = s0c12;
            dst[(row+16)*4 + 0] = s1hd0;
            dst[(row+16)*4 + 1] = s1c00;
            dst[(row+16)*4 + 2] = s1c01;
            dst[(row+16)*4 + 3] = s1c02;
            dst[(row+24)*4 + 0] = s1hd1;
            dst[(row+24)*4 + 1] = s1c10;
            dst[(row+24)*4 + 2] = s1c11;
            dst[(row+24)*4 + 3] = s1c12;
        }
        __syncthreads();   // sHA/sHB/sTS/sMSK/sRAY ready block-wide

        // ======== EPILOGUE (threads < 128; tid = sample row) ========
        float my_sd = 0.0f, mc0 = 0.0f, mc1 = 0.0f, mc2 = 0.0f;
        if (tid < TSAMP) {
            float e_tfar_c = sRAY[0];
            float e_dnorm = sRAY[1];
            float edx = sRAY[3], edy = sRAY[4], edz = sRAY[5];

            float accd = sHA[tid*4 + 0] + sHB[tid*4 + 0];
            float ac0  = sHA[tid*4 + 1] + sHB[tid*4 + 1];
            float ac1  = sHA[tid*4 + 2] + sHB[tid*4 + 2];
            float ac2  = sHA[tid*4 + 3] + sHB[tid*4 + 3];
            float inv_n = 1.0f / e_dnorm;
            float Ysh[16];
            sh3(edx*inv_n, edy*inv_n, edz*inv_n, Ysh);
            #pragma unroll
            for (int q = 0; q < SHDIM; q++) {
                float wq = Ysh[q];
                ac0 = fmaf(wq, sWC[(HID + q)*3 + 0], ac0);
                ac1 = fmaf(wq, sWC[(HID + q)*3 + 1], ac1);
                ac2 = fmaf(wq, sWC[(HID + q)*3 + 2], ac2);
            }
            float zz = accd + sBC[3];
            float sig = fmaxf(zz, 0.0f) + log1pf(expf(-fabsf(zz)));
            float m = sMSK[tid];
            sig *= m;
            mc0 = m / (1.0f + expf(-(ac0 + sBC[0])));
            mc1 = m / (1.0f + expf(-(ac1 + sBC[1])));
            mc2 = m / (1.0f + expf(-(ac2 + sBC[2])));
            float tsv  = sTS[tid];
            float tnxt = (tid < TSAMP - 1) ? sTS[tid + 1] : (e_tfar_c * RAYEXT);
            my_sd = sig * (tnxt - tsv) * e_dnorm;
        }

        // inclusive scan over 128 samples (warps 0-3 carry data)
        float v = my_sd;
        #pragma unroll
        for (int o = 1; o < 32; o <<= 1) {
            float n = __shfl_up_sync(0xffffffffu, v, o);
            if (lane >= o) v += n;
        }
        if (wid < 4 && lane == 31) sWS[wid] = v;
        __syncthreads();
        float woff = 0.0f;
        if (wid < 4) {
            #pragma unroll
            for (int q = 0; q < 4; q++) woff += (q < wid) ? sWS[q] : 0.0f;
        }
        float csum = v + woff;

        float wgt = 0.0f;
        if (tid < TSAMP) wgt = expf(my_sd - csum) - expf(-csum);
        float rc0 = wgt * mc0, rc1 = wgt * mc1, rc2 = wgt * mc2;

        #pragma unroll
        for (int o = 16; o; o >>= 1) {
            rc0 += __shfl_xor_sync(0xffffffffu, rc0, o);
            rc1 += __shfl_xor_sync(0xffffffffu, rc1, o);
            rc2 += __shfl_xor_sync(0xffffffffu, rc2, o);
            wgt += __shfl_xor_sync(0xffffffffu, wgt, o);
        }
        if (wid < 4 && lane == 0) {
            sRED[wid*4 + 0] = rc0;
            sRED[wid*4 + 1] = rc1;
            sRED[wid*4 + 2] = rc2;
            sRED[wid*4 + 3] = wgt;
        }
        __syncthreads();
        if (tid == 0) {
            float o0 = 0.0f, o1 = 0.0f, o2 = 0.0f, o3 = 0.0f;
            #pragma unroll
            for (int q = 0; q < 4; q++) {
                o0 += sRED[q*4 + 0];
                o1 += sRED[q*4 + 1];
                o2 += sRED[q*4 + 2];
                o3 += sRED[q*4 + 3];
            }
            bool act = (sRAY[2] != 0.0f);
            float4 res;
            res.x = act ? o0 : 0.0f;
            res.y = act ? o1 : 0.0f;
            res.z = act ? o2 : 0.0f;
            res.w = act ? o3 : 0.0f;
            *(float4*)(out + (size_t)r*4) = res;
        }
        __syncthreads();   // protect shared scratch before next iteration
    }
}

extern "C" void kernel_launch(void* const* d_in, const int* in_sizes, int n_in,
                              void* d_out, int out_size) {
    const float* origins = (const float*)d_in[0];
    const float* dirs    = (const float*)d_in[1];
    const float* u       = (const float*)d_in[2];
    const float* W1      = (const float*)d_in[3];
    const float* b1      = (const float*)d_in[4];
    const float* W2      = (const float*)d_in[5];
    const float* b2      = (const float*)d_in[6];
    const float* Wd      = (const float*)d_in[7];
    const float* bd      = (const float*)d_in[8];
    const float* Wc      = (const float*)d_in[9];
    const float* bc      = (const float*)d_in[10];
    float* out = (float*)d_out;

    int dev = 0, nsm = 148;
    cudaGetDevice(&dev);
    cudaDeviceGetAttribute(&nsm, cudaDevAttrMultiProcessorCount, dev);

    cudaFuncSetAttribute(radiance_kernel,
                         cudaFuncAttributeMaxDynamicSharedMemorySize, SMEM_BYTES);
    radiance_kernel<<<nsm * 2, NTHREADS, SMEM_BYTES>>>(
        origins, dirs, u, W1, b1, W2, b2, Wd, bd, Wc, bc, out);
}